// round 1
// baseline (speedup 1.0000x reference)
#include <cuda_runtime.h>
#include <cstdint>
#include <cstddef>

#define BB 8
#define NN 2048
#define IND 256
#define DD 64
#define ALPHA 0.2f

#define TILE_J 64
#define WARPS 4
#define RPW 8
#define TILE_I (WARPS * RPW)  // 32

// Scratch (device globals: allocation-free)
__device__ float g_Wh[BB * NN * DD];   // 4 MB
__device__ float g_s1[BB * NN];
__device__ float g_s2[BB * NN];

// ---- f32x2 packed helpers (PTX-only path; ptxas won't auto-fuse) ----
__device__ __forceinline__ unsigned long long pack2(float x, float y) {
    unsigned long long d;
    asm("mov.b64 %0, {%1, %2};" : "=l"(d) : "f"(x), "f"(y));
    return d;
}
__device__ __forceinline__ unsigned long long ffma2(unsigned long long a,
                                                    unsigned long long b,
                                                    unsigned long long c) {
    unsigned long long d;
    asm("fma.rn.f32x2 %0, %1, %2, %3;" : "=l"(d) : "l"(a), "l"(b), "l"(c));
    return d;
}
__device__ __forceinline__ float lo32(unsigned long long v) {
    return __uint_as_float((unsigned)(v & 0xffffffffull));
}
__device__ __forceinline__ float hi32(unsigned long long v) {
    return __uint_as_float((unsigned)(v >> 32));
}

// ================= Kernel 1: Wh = h @ W =================
// 256 threads, 16 rows/block. h tile in smem; W streamed through L1/L2.
__global__ void __launch_bounds__(256) wh_kernel(const float* __restrict__ h,
                                                 const float* __restrict__ W) {
    __shared__ float hs[16][IND];  // 16 KB
    const int row0 = blockIdx.x * 16;
    const int tid = threadIdx.x;

    const float4* hg = (const float4*)(h + (size_t)row0 * IND);
    float4* hs4 = (float4*)&hs[0][0];
#pragma unroll
    for (int t = 0; t < 4; t++) hs4[tid + 256 * t] = hg[tid + 256 * t];
    __syncthreads();

    const int c = tid & 63;
    const int rq = tid >> 6;  // 0..3
    float acc[4] = {0.f, 0.f, 0.f, 0.f};
#pragma unroll 4
    for (int k = 0; k < IND; k++) {
        const float w = __ldg(&W[k * DD + c]);
#pragma unroll
        for (int rr = 0; rr < 4; rr++)
            acc[rr] = fmaf(hs[rq + 4 * rr][k], w, acc[rr]);
    }
#pragma unroll
    for (int rr = 0; rr < 4; rr++)
        g_Wh[(size_t)(row0 + rq + 4 * rr) * DD + c] = acc[rr];
}

// ================= Kernel 2: s1/s2 = Wh @ a1 / a2 =================
// warp per row
__global__ void __launch_bounds__(256) s_kernel(const float* __restrict__ a) {
    const int warp = threadIdx.x >> 5, lane = threadIdx.x & 31;
    const int row = blockIdx.x * 8 + warp;
    const float2 wh = ((const float2*)(g_Wh + (size_t)row * DD))[lane];
    const float2 a1 = ((const float2*)a)[lane];
    const float2 a2 = ((const float2*)(a + DD))[lane];
    float s1 = wh.x * a1.x + wh.y * a1.y;
    float s2 = wh.x * a2.x + wh.y * a2.y;
#pragma unroll
    for (int o = 16; o > 0; o >>= 1) {
        s1 += __shfl_xor_sync(0xffffffffu, s1, o);
        s2 += __shfl_xor_sync(0xffffffffu, s2, o);
    }
    if (lane == 0) { g_s1[row] = s1; g_s2[row] = s2; }
}

// ================= Kernel 3: fused masked softmax x Wh =================
// 128 threads = 4 warps; each warp owns 8 i-rows; j tiled by 64.
// p values stored in smem pre-duplicated as (p,p) f32x2 so the MAC loop is
// 1 LDS.64(wh) + 8 LDS.64(p bcast) + 8 FFMA2 per j-step (64 MACs/FFMA2-instr*... 512 MACs / 8 instrs).
__global__ void __launch_bounds__(128) attn_kernel(const int* __restrict__ adj,
                                                   float* __restrict__ out) {
    __shared__ float wh_s[TILE_J][DD];                         // 16 KB
    __shared__ float s2_s[TILE_J];
    __shared__ unsigned long long p_s[WARPS][RPW][TILE_J];     // 16 KB (packed p,p)

    const int b = blockIdx.x / (NN / TILE_I);
    const int i0 = (blockIdx.x % (NN / TILE_I)) * TILE_I;
    const int tid = threadIdx.x;
    const int w = tid >> 5, l = tid & 31;

    float s1v[RPW];
    float den[RPW];
    unsigned long long acc[RPW];
#pragma unroll
    for (int r = 0; r < RPW; r++) {
        s1v[r] = g_s1[b * NN + i0 + w * RPW + r];
        den[r] = 0.f;
        acc[r] = 0ull;
    }
    const size_t adj_base = ((size_t)b * NN + i0 + w * RPW) * NN;

    for (int jt = 0; jt < NN / TILE_J; jt++) {
        const int j0 = jt * TILE_J;
        __syncthreads();  // previous tile's MAC done before overwriting wh_s
        {
            const float4* src = (const float4*)(g_Wh + ((size_t)b * NN + j0) * DD);
            float4* dst = (float4*)&wh_s[0][0];
#pragma unroll
            for (int t = 0; t < 8; t++) dst[tid + 128 * t] = src[tid + 128 * t];
            if (tid < TILE_J) s2_s[tid] = g_s2[b * NN + j0 + tid];
        }
        __syncthreads();

        // ---- Phase A: p = adj ? exp(lrelu(s1+s2)) : 0 ----
        const float2 s2p = *(const float2*)&s2_s[2 * l];
#pragma unroll
        for (int r = 0; r < RPW; r++) {
            const int2 av = *(const int2*)(adj + adj_base + (size_t)r * NN + j0 + 2 * l);
            float e0 = s1v[r] + s2p.x;
            float e1 = s1v[r] + s2p.y;
            e0 = fmaxf(e0, ALPHA * e0);   // leaky relu (ALPHA<1)
            e1 = fmaxf(e1, ALPHA * e1);
            const float p0 = av.x ? __expf(e0) : 0.f;
            const float p1 = av.y ? __expf(e1) : 0.f;
            den[r] += p0 + p1;
            // duplicated pack, 16B store (conflict-minimal)
            ulonglong2 v;
            v.x = pack2(p0, p0);
            v.y = pack2(p1, p1);
            *(ulonglong2*)&p_s[w][r][2 * l] = v;
        }
        __syncwarp();

        // ---- Phase B: acc += p * Wh  (f32x2, 8-row register block) ----
#pragma unroll 4
        for (int j = 0; j < TILE_J; j++) {
            const unsigned long long wh2 =
                *(const unsigned long long*)&wh_s[j][2 * l];
#pragma unroll
            for (int r = 0; r < RPW; r++) {
                acc[r] = ffma2(p_s[w][r][j], wh2, acc[r]);  // broadcast LDS
            }
        }
        __syncwarp();
    }

    // ---- Epilogue: normalize and store ----
#pragma unroll
    for (int r = 0; r < RPW; r++) {
        float d = den[r];
#pragma unroll
        for (int o = 16; o > 0; o >>= 1) d += __shfl_xor_sync(0xffffffffu, d, o);
        const float inv = 1.0f / d;
        const int i = i0 + w * RPW + r;
        ((float2*)(out + ((size_t)b * NN + i) * DD))[l] =
            make_float2(lo32(acc[r]) * inv, hi32(acc[r]) * inv);
    }
}

extern "C" void kernel_launch(void* const* d_in, const int* in_sizes, int n_in,
                              void* d_out, int out_size) {
    // Defensive input mapping by element count (all four are distinct)
    const float* h = nullptr; const int* adj = nullptr;
    const float* W = nullptr; const float* a = nullptr;
    for (int i = 0; i < n_in; i++) {
        const long long s = in_sizes[i];
        if (s == (long long)BB * NN * IND)      h   = (const float*)d_in[i];
        else if (s == (long long)BB * NN * NN)  adj = (const int*)d_in[i];
        else if (s == (long long)IND * DD)      W   = (const float*)d_in[i];
        else if (s == 2 * DD)                   a   = (const float*)d_in[i];
    }
    float* out = (float*)d_out;

    wh_kernel<<<(BB * NN) / 16, 256>>>(h, W);
    s_kernel<<<(BB * NN) / 8, 256>>>(a);
    attn_kernel<<<BB * (NN / TILE_I), 128>>>(adj, out);
}

// round 3
// speedup vs baseline: 1.6489x; 1.6489x over previous
#include <cuda_runtime.h>
#include <cuda_bf16.h>
#include <cstdint>
#include <cstddef>

#define BB 8
#define NN 2048
#define IND 256
#define DD 64
#define ALPHA 0.2f
#define KTILE 64
#define NKT (NN / KTILE)   // 32

// ---------------- device scratch (allocation-free) ----------------
__device__ float g_s1[BB * NN];
__device__ float g_s2[BB * NN];
__device__ __nv_bfloat16 g_Bhi[(size_t)BB * DD * NN];  // [b][d][j], K-major B operand
__device__ __nv_bfloat16 g_Blo[(size_t)BB * DD * NN];

// ---------------- helpers ----------------
__device__ __forceinline__ uint32_t smem_u32(const void* p) {
    uint32_t a;
    asm("{ .reg .u64 t; cvta.to.shared.u64 t, %1; cvt.u32.u64 %0, t; }"
        : "=r"(a) : "l"(p));
    return a;
}
__device__ __forceinline__ unsigned long long pack2(float x, float y) {
    unsigned long long d;
    asm("mov.b64 %0, {%1, %2};" : "=l"(d) : "f"(x), "f"(y));
    return d;
}
__device__ __forceinline__ unsigned long long ffma2(unsigned long long a,
                                                    unsigned long long b,
                                                    unsigned long long c) {
    unsigned long long d;
    asm("fma.rn.f32x2 %0, %1, %2, %3;" : "=l"(d) : "l"(a), "l"(b), "l"(c));
    return d;
}
__device__ __forceinline__ float lo32(unsigned long long v) {
    return __uint_as_float((unsigned)(v & 0xffffffffull));
}
__device__ __forceinline__ float hi32(unsigned long long v) {
    return __uint_as_float((unsigned)(v >> 32));
}
// pack (first, second) -> bf16x2 with first in LOW half
__device__ __forceinline__ uint32_t bf2(float first, float second) {
    uint32_t r;
    asm("cvt.rn.bf16x2.f32 %0, %1, %2;" : "=r"(r) : "f"(second), "f"(first));
    return r;
}
__device__ __forceinline__ uint32_t sw128(uint32_t off) {
    return off ^ ((off >> 3) & 0x70);
}
__device__ __forceinline__ void sts128(uint32_t addr, uint4 v) {
    asm volatile("st.shared.v4.b32 [%0], {%1,%2,%3,%4};"
                 :: "r"(addr), "r"(v.x), "r"(v.y), "r"(v.z), "r"(v.w) : "memory");
}
__device__ __forceinline__ void ldmx4(uint32_t& r0, uint32_t& r1, uint32_t& r2,
                                      uint32_t& r3, uint32_t addr) {
    asm volatile("ldmatrix.sync.aligned.m8n8.x4.shared.b16 {%0,%1,%2,%3}, [%4];"
                 : "=r"(r0), "=r"(r1), "=r"(r2), "=r"(r3) : "r"(addr));
}
__device__ __forceinline__ void mma16816(float* d, uint32_t a0, uint32_t a1,
                                         uint32_t a2, uint32_t a3, uint32_t b0,
                                         uint32_t b1) {
    asm volatile(
        "mma.sync.aligned.m16n8k16.row.col.f32.bf16.bf16.f32 "
        "{%0,%1,%2,%3}, {%4,%5,%6,%7}, {%8,%9}, {%0,%1,%2,%3};"
        : "+f"(d[0]), "+f"(d[1]), "+f"(d[2]), "+f"(d[3])
        : "r"(a0), "r"(a1), "r"(a2), "r"(a3), "r"(b0), "r"(b1));
}
__device__ __forceinline__ float pe(float e, int m) {
    e = fmaxf(e, ALPHA * e);
    return m ? __expf(e) : 0.f;
}

// ================= Kernel 1: fused Wh + s1/s2 + bf16-split B operand =================
// 32 rows per CTA, f32x2 MAC loop.
__global__ void __launch_bounds__(256) wh_kernel(const float* __restrict__ h,
                                                 const float* __restrict__ W,
                                                 const float* __restrict__ a) {
    __shared__ float hs[32][260];   // 33.3 KB
    __shared__ float ws[32][68];    // 8.7 KB
    const int tid = threadIdx.x;
    const int row0 = blockIdx.x * 32;

    // stage h tile (32 x 256)
#pragma unroll
    for (int q = 0; q < 8; q++) {
        const int e = tid + 256 * q;
        const int r = e >> 6, kc = (e & 63) * 4;
        *(float4*)&hs[r][kc] = *(const float4*)&h[(size_t)(row0 + r) * IND + kc];
    }
    __syncthreads();

    const int c = tid & 63, rq = tid >> 6;
    unsigned long long acc[8];
#pragma unroll
    for (int rr = 0; rr < 8; rr++) acc[rr] = 0ull;

#pragma unroll 4
    for (int k2 = 0; k2 < IND / 2; k2++) {
        const float w0 = __ldg(&W[(2 * k2) * DD + c]);      // coalesced, L1-resident
        const float w1 = __ldg(&W[(2 * k2 + 1) * DD + c]);
        const unsigned long long w2 = pack2(w0, w1);
#pragma unroll
        for (int rr = 0; rr < 8; rr++) {
            const unsigned long long hv =
                *(const unsigned long long*)&hs[rq * 8 + rr][2 * k2];
            acc[rr] = ffma2(hv, w2, acc[rr]);
        }
    }
#pragma unroll
    for (int rr = 0; rr < 8; rr++)
        ws[rq * 8 + rr][c] = lo32(acc[rr]) + hi32(acc[rr]);
    __syncthreads();

    // ---- s1/s2: warp w handles rows 4w..4w+3 ----
    {
        const int w = tid >> 5, l = tid & 31;
        const int row = 4 * w + (l >> 3);
        const int c8 = (l & 7) * 8;
        const float4 v0 = *(float4*)&ws[row][c8];
        const float4 v1 = *(float4*)&ws[row][c8 + 4];
        const float4 x0 = *(const float4*)&a[c8];
        const float4 x1 = *(const float4*)&a[c8 + 4];
        const float4 y0 = *(const float4*)&a[DD + c8];
        const float4 y1 = *(const float4*)&a[DD + c8 + 4];
        float s1p = v0.x * x0.x + v0.y * x0.y + v0.z * x0.z + v0.w * x0.w +
                    v1.x * x1.x + v1.y * x1.y + v1.z * x1.z + v1.w * x1.w;
        float s2p = v0.x * y0.x + v0.y * y0.y + v0.z * y0.z + v0.w * y0.w +
                    v1.x * y1.x + v1.y * y1.y + v1.z * y1.z + v1.w * y1.w;
#pragma unroll
        for (int o = 1; o < 8; o <<= 1) {
            s1p += __shfl_xor_sync(0xffffffffu, s1p, o);
            s2p += __shfl_xor_sync(0xffffffffu, s2p, o);
        }
        if ((l & 7) == 0) {
            g_s1[row0 + row] = s1p;
            g_s2[row0 + row] = s2p;
        }
    }

    // ---- bf16-split transpose: thread d = tid&63 writes 8 j's (rows rg*8..+7) ----
    {
        const int d = tid & 63, rg = tid >> 6;
        const size_t b = (size_t)(row0 >> 11);
        const int j0l = (row0 & (NN - 1)) + rg * 8;
        uint32_t hi4[4], lo4[4];
#pragma unroll
        for (int p = 0; p < 4; p++) {
            const float p0 = ws[rg * 8 + 2 * p][d];
            const float p1 = ws[rg * 8 + 2 * p + 1][d];
            const uint32_t h2 = bf2(p0, p1);
            const float f0 = __uint_as_float(h2 << 16);
            const float f1 = __uint_as_float(h2 & 0xffff0000u);
            hi4[p] = h2;
            lo4[p] = bf2(p0 - f0, p1 - f1);
        }
        const size_t off = ((b * DD + d) * NN + j0l) * 2;
        *(uint4*)((char*)g_Bhi + off) = make_uint4(hi4[0], hi4[1], hi4[2], hi4[3]);
        *(uint4*)((char*)g_Blo + off) = make_uint4(lo4[0], lo4[1], lo4[2], lo4[3]);
    }
}

// ================= Kernel 2: fused masked-softmax x Wh via mma.sync =================
struct AttnState {
    float acc[8][4];
    float den0, den1;
    float s1_0, s1_1;
    int c0;
    uint32_t nbase[4];   // smem base + n*128 per np (lane-dependent)
    uint32_t nxor[4];
    uint32_t kh;         // (lane-group&1)*16
    const float* s2base;
};

__device__ __forceinline__ void compute_tile(AttnState& st, int t,
                                             const int2 aj[4][4]) {
#pragma unroll
    for (int ks = 0; ks < 4; ks++) {
        const int jb = t * KTILE + ks * 16;
        const float2 s2a = *(const float2*)(st.s2base + jb + st.c0);
        const float2 s2b = *(const float2*)(st.s2base + jb + st.c0 + 8);
        const int2 A0 = aj[ks][0], A1 = aj[ks][1], A2 = aj[ks][2], A3 = aj[ks][3];

        float p0 = pe(st.s1_0 + s2a.x, A0.x);
        float p1 = pe(st.s1_0 + s2a.y, A0.y);
        float p2 = pe(st.s1_0 + s2b.x, A1.x);
        float p3 = pe(st.s1_0 + s2b.y, A1.y);
        float p4 = pe(st.s1_1 + s2a.x, A2.x);
        float p5 = pe(st.s1_1 + s2a.y, A2.y);
        float p6 = pe(st.s1_1 + s2b.x, A3.x);
        float p7 = pe(st.s1_1 + s2b.y, A3.y);
        st.den0 += (p0 + p1) + (p2 + p3);
        st.den1 += (p4 + p5) + (p6 + p7);

        // A fragments: a0=(r0,c0,c0+1) a1=(r1,c0,c0+1) a2=(r0,c0+8,+9) a3=(r1,c0+8,+9)
        uint32_t ah[4], al[4];
        {
            const uint32_t h0 = bf2(p0, p1), h1 = bf2(p4, p5);
            const uint32_t h2 = bf2(p2, p3), h3 = bf2(p6, p7);
            ah[0] = h0; ah[1] = h1; ah[2] = h2; ah[3] = h3;
            al[0] = bf2(p0 - __uint_as_float(h0 << 16),
                        p1 - __uint_as_float(h0 & 0xffff0000u));
            al[1] = bf2(p4 - __uint_as_float(h1 << 16),
                        p5 - __uint_as_float(h1 & 0xffff0000u));
            al[2] = bf2(p2 - __uint_as_float(h2 << 16),
                        p3 - __uint_as_float(h2 & 0xffff0000u));
            al[3] = bf2(p6 - __uint_as_float(h3 << 16),
                        p7 - __uint_as_float(h3 & 0xffff0000u));
        }

#pragma unroll
        for (int np = 0; np < 4; np++) {
            const uint32_t off = (uint32_t)((ks * 32 + st.kh)) ^ st.nxor[np];
            uint32_t h0, h1, h2, h3, l0, l1, l2, l3;
            ldmx4(h0, h1, h2, h3, st.nbase[np] + off);
            ldmx4(l0, l1, l2, l3, st.nbase[np] + off + 8192);
            mma16816(st.acc[2 * np], ah[0], ah[1], ah[2], ah[3], h0, h1);
            mma16816(st.acc[2 * np], al[0], al[1], al[2], al[3], h0, h1);
            mma16816(st.acc[2 * np], ah[0], ah[1], ah[2], ah[3], l0, l1);
            mma16816(st.acc[2 * np + 1], ah[0], ah[1], ah[2], ah[3], h2, h3);
            mma16816(st.acc[2 * np + 1], al[0], al[1], al[2], al[3], h2, h3);
            mma16816(st.acc[2 * np + 1], ah[0], ah[1], ah[2], ah[3], l2, l3);
        }
    }
}

#define LOADB(t)                                                                 \
    do {                                                                         \
        pre[0] = *(const uint4*)(gbh + ((size_t)d0 * NN + (t) * KTILE) * 2 + ch0 * 16); \
        pre[1] = *(const uint4*)(gbh + ((size_t)d1 * NN + (t) * KTILE) * 2 + ch1 * 16); \
        pre[2] = *(const uint4*)(gbl + ((size_t)d0 * NN + (t) * KTILE) * 2 + ch0 * 16); \
        pre[3] = *(const uint4*)(gbl + ((size_t)d1 * NN + (t) * KTILE) * 2 + ch1 * 16); \
    } while (0)

#define LOADADJ(dst, t)                                                          \
    do {                                                                         \
        _Pragma("unroll")                                                        \
        for (int ks = 0; ks < 4; ks++) {                                         \
            const int jc = (t) * KTILE + ks * 16 + st.c0;                        \
            dst[ks][0] = *(const int2*)(arow0 + jc);                             \
            dst[ks][1] = *(const int2*)(arow0 + jc + 8);                         \
            dst[ks][2] = *(const int2*)(arow1 + jc);                             \
            dst[ks][3] = *(const int2*)(arow1 + jc + 8);                         \
        }                                                                        \
    } while (0)

#define STAGEB()                                                                 \
    do {                                                                         \
        __syncthreads();                                                         \
        sts128(sa0, pre[0]);                                                     \
        sts128(sa1, pre[1]);                                                     \
        sts128(sa0 + 8192, pre[2]);                                              \
        sts128(sa1 + 8192, pre[3]);                                              \
        __syncthreads();                                                         \
    } while (0)

__global__ void __launch_bounds__(256) attn_kernel(const int* __restrict__ adj,
                                                   float* __restrict__ out) {
    __shared__ __align__(128) uint8_t Bs[16384];  // hi @0, lo @8192

    const int tid = threadIdx.x, wid = tid >> 5, lid = tid & 31;
    const int b = blockIdx.x >> 4;
    const int i0 = (blockIdx.x & 15) * 128;
    const int ibase = i0 + wid * 16;
    const int r0 = lid >> 2;

    AttnState st;
    st.c0 = (lid & 3) * 2;
    st.s1_0 = g_s1[b * NN + ibase + r0];
    st.s1_1 = g_s1[b * NN + ibase + r0 + 8];
    st.den0 = 0.f;
    st.den1 = 0.f;
    st.s2base = g_s2 + b * NN;
#pragma unroll
    for (int nt = 0; nt < 8; nt++)
#pragma unroll
        for (int q = 0; q < 4; q++) st.acc[nt][q] = 0.f;

    const uint32_t sb = smem_u32(Bs);
    {
        const int g = lid >> 3, rowin = lid & 7;
        st.kh = (uint32_t)((g & 1) * 16);
#pragma unroll
        for (int np = 0; np < 4; np++) {
            const int n = np * 16 + (g >> 1) * 8 + rowin;
            st.nbase[np] = sb + n * 128;
            st.nxor[np] = (uint32_t)((n & 7) << 4);
        }
    }

    const char* gbh = (const char*)g_Bhi + (size_t)b * DD * NN * 2;
    const char* gbl = (const char*)g_Blo + (size_t)b * DD * NN * 2;
    const int e0 = tid * 2, d0 = e0 >> 3, ch0 = e0 & 7;
    const int e1 = tid * 2 + 1, d1 = e1 >> 3, ch1 = e1 & 7;
    const uint32_t sa0 = sb + sw128((uint32_t)(d0 * 128 + ch0 * 16));
    const uint32_t sa1 = sb + sw128((uint32_t)(d1 * 128 + ch1 * 16));

    const int* arow0 = adj + (size_t)(b * NN + ibase + r0) * NN;
    const int* arow1 = arow0 + (size_t)8 * NN;

    uint4 pre[4];
    int2 ajA[4][4], ajB[4][4];

    LOADB(0);
    LOADADJ(ajA, 0);

    for (int t2 = 0; t2 < NKT / 2; t2++) {
        const int ta = 2 * t2, tb = 2 * t2 + 1;
        STAGEB();
        LOADB(tb);
        LOADADJ(ajB, tb);
        compute_tile(st, ta, ajA);

        STAGEB();
        if (tb + 1 < NKT) {
            LOADB(tb + 1);
            LOADADJ(ajA, tb + 1);
        }
        compute_tile(st, tb, ajB);
    }

    // ---- epilogue: reduce den over the 4 lanes sharing r0, normalize, store ----
    st.den0 += __shfl_xor_sync(0xffffffffu, st.den0, 1);
    st.den0 += __shfl_xor_sync(0xffffffffu, st.den0, 2);
    st.den1 += __shfl_xor_sync(0xffffffffu, st.den1, 1);
    st.den1 += __shfl_xor_sync(0xffffffffu, st.den1, 2);
    const float inv0 = 1.0f / st.den0;
    const float inv1 = 1.0f / st.den1;

    float* o0 = out + (size_t)(b * NN + ibase + r0) * DD;
    float* o1 = o0 + (size_t)8 * DD;
#pragma unroll
    for (int nt = 0; nt < 8; nt++) {
        *(float2*)(o0 + nt * 8 + st.c0) =
            make_float2(st.acc[nt][0] * inv0, st.acc[nt][1] * inv0);
        *(float2*)(o1 + nt * 8 + st.c0) =
            make_float2(st.acc[nt][2] * inv1, st.acc[nt][3] * inv1);
    }
}

extern "C" void kernel_launch(void* const* d_in, const int* in_sizes, int n_in,
                              void* d_out, int out_size) {
    const float* h = nullptr;
    const int* adj = nullptr;
    const float* W = nullptr;
    const float* a = nullptr;
    for (int i = 0; i < n_in; i++) {
        const long long s = in_sizes[i];
        if (s == (long long)BB * NN * IND)      h   = (const float*)d_in[i];
        else if (s == (long long)BB * NN * NN)  adj = (const int*)d_in[i];
        else if (s == (long long)IND * DD)      W   = (const float*)d_in[i];
        else if (s == 2 * DD)                   a   = (const float*)d_in[i];
    }
    float* out = (float*)d_out;

    wh_kernel<<<(BB * NN) / 32, 256>>>(h, W, a);
    attn_kernel<<<BB * (NN / 128), 256>>>(adj, out);
}

// round 6
// speedup vs baseline: 2.3253x; 1.4103x over previous
#include <cuda_runtime.h>
#include <cuda_bf16.h>
#include <cstdint>
#include <cstddef>

#define BB 8
#define NN 2048
#define IND 256
#define DD 64
#define ALPHA 0.2f
#define KTILE 64
#define NKT (NN / KTILE)   // 32

// ---------------- device scratch (allocation-free) ----------------
__device__ float g_s1[BB * NN];
__device__ float g_s2[BB * NN];
__device__ __nv_bfloat16 g_Bhi[(size_t)BB * DD * NN];  // [b][d][j], K-major B operand
__device__ __nv_bfloat16 g_Blo[(size_t)BB * DD * NN];

// ---------------- helpers ----------------
__device__ __forceinline__ uint32_t smem_u32(const void* p) {
    uint32_t a;
    asm("{ .reg .u64 t; cvta.to.shared.u64 t, %1; cvt.u32.u64 %0, t; }"
        : "=r"(a) : "l"(p));
    return a;
}
__device__ __forceinline__ unsigned long long pack2(float x, float y) {
    unsigned long long d;
    asm("mov.b64 %0, {%1, %2};" : "=l"(d) : "f"(x), "f"(y));
    return d;
}
__device__ __forceinline__ unsigned long long ffma2(unsigned long long a,
                                                    unsigned long long b,
                                                    unsigned long long c) {
    unsigned long long d;
    asm("fma.rn.f32x2 %0, %1, %2, %3;" : "=l"(d) : "l"(a), "l"(b), "l"(c));
    return d;
}
__device__ __forceinline__ float lo32(unsigned long long v) {
    return __uint_as_float((unsigned)(v & 0xffffffffull));
}
__device__ __forceinline__ float hi32(unsigned long long v) {
    return __uint_as_float((unsigned)(v >> 32));
}
// pack (first, second) -> bf16x2 with first in LOW half
__device__ __forceinline__ uint32_t bf2(float first, float second) {
    uint32_t r;
    asm("cvt.rn.bf16x2.f32 %0, %1, %2;" : "=r"(r) : "f"(second), "f"(first));
    return r;
}
__device__ __forceinline__ uint32_t sw128(uint32_t off) {
    return off ^ ((off >> 3) & 0x70);
}
__device__ __forceinline__ void ldmx4(uint32_t& r0, uint32_t& r1, uint32_t& r2,
                                      uint32_t& r3, uint32_t addr) {
    asm volatile("ldmatrix.sync.aligned.m8n8.x4.shared.b16 {%0,%1,%2,%3}, [%4];"
                 : "=r"(r0), "=r"(r1), "=r"(r2), "=r"(r3) : "r"(addr));
}
__device__ __forceinline__ void mma16816(float* d, uint32_t a0, uint32_t a1,
                                         uint32_t a2, uint32_t a3, uint32_t b0,
                                         uint32_t b1) {
    asm volatile(
        "mma.sync.aligned.m16n8k16.row.col.f32.bf16.bf16.f32 "
        "{%0,%1,%2,%3}, {%4,%5,%6,%7}, {%8,%9}, {%0,%1,%2,%3};"
        : "+f"(d[0]), "+f"(d[1]), "+f"(d[2]), "+f"(d[3])
        : "r"(a0), "r"(a1), "r"(a2), "r"(a3), "r"(b0), "r"(b1));
}
__device__ __forceinline__ float pe(float e, int m) {
    e = fmaxf(e, ALPHA * e);
    return m ? __expf(e) : 0.f;
}
__device__ __forceinline__ void cpa16(uint32_t dst, const void* src) {
    asm volatile("cp.async.cg.shared.global [%0], [%1], 16;"
                 :: "r"(dst), "l"(src) : "memory");
}
__device__ __forceinline__ void cpa_commit() {
    asm volatile("cp.async.commit_group;" ::: "memory");
}
__device__ __forceinline__ void cpa_wait0() {
    asm volatile("cp.async.wait_group 0;" ::: "memory");
}

// ================= Kernel 1: fused Wh + s1/s2 + bf16-split B operand =================
__global__ void __launch_bounds__(256) wh_kernel(const float* __restrict__ h,
                                                 const float* __restrict__ W,
                                                 const float* __restrict__ a) {
    __shared__ float hs[32][260];
    __shared__ float ws[32][68];
    const int tid = threadIdx.x;
    const int row0 = blockIdx.x * 32;

#pragma unroll
    for (int q = 0; q < 8; q++) {
        const int e = tid + 256 * q;
        const int r = e >> 6, kc = (e & 63) * 4;
        *(float4*)&hs[r][kc] = *(const float4*)&h[(size_t)(row0 + r) * IND + kc];
    }
    __syncthreads();

    const int c = tid & 63, rq = tid >> 6;
    unsigned long long acc[8];
#pragma unroll
    for (int rr = 0; rr < 8; rr++) acc[rr] = 0ull;

#pragma unroll 4
    for (int k2 = 0; k2 < IND / 2; k2++) {
        const float w0 = __ldg(&W[(2 * k2) * DD + c]);
        const float w1 = __ldg(&W[(2 * k2 + 1) * DD + c]);
        const unsigned long long w2 = pack2(w0, w1);
#pragma unroll
        for (int rr = 0; rr < 8; rr++) {
            const unsigned long long hv =
                *(const unsigned long long*)&hs[rq * 8 + rr][2 * k2];
            acc[rr] = ffma2(hv, w2, acc[rr]);
        }
    }
#pragma unroll
    for (int rr = 0; rr < 8; rr++)
        ws[rq * 8 + rr][c] = lo32(acc[rr]) + hi32(acc[rr]);
    __syncthreads();

    {
        const int w = tid >> 5, l = tid & 31;
        const int row = 4 * w + (l >> 3);
        const int c8 = (l & 7) * 8;
        const float4 v0 = *(float4*)&ws[row][c8];
        const float4 v1 = *(float4*)&ws[row][c8 + 4];
        const float4 x0 = *(const float4*)&a[c8];
        const float4 x1 = *(const float4*)&a[c8 + 4];
        const float4 y0 = *(const float4*)&a[DD + c8];
        const float4 y1 = *(const float4*)&a[DD + c8 + 4];
        float s1p = v0.x * x0.x + v0.y * x0.y + v0.z * x0.z + v0.w * x0.w +
                    v1.x * x1.x + v1.y * x1.y + v1.z * x1.z + v1.w * x1.w;
        float s2p = v0.x * y0.x + v0.y * y0.y + v0.z * y0.z + v0.w * y0.w +
                    v1.x * y1.x + v1.y * y1.y + v1.z * y1.z + v1.w * y1.w;
#pragma unroll
        for (int o = 1; o < 8; o <<= 1) {
            s1p += __shfl_xor_sync(0xffffffffu, s1p, o);
            s2p += __shfl_xor_sync(0xffffffffu, s2p, o);
        }
        if ((l & 7) == 0) {
            g_s1[row0 + row] = s1p;
            g_s2[row0 + row] = s2p;
        }
    }

    {
        const int d = tid & 63, rg = tid >> 6;
        const size_t b = (size_t)(row0 >> 11);
        const int j0l = (row0 & (NN - 1)) + rg * 8;
        uint32_t hi4[4], lo4[4];
#pragma unroll
        for (int p = 0; p < 4; p++) {
            const float p0 = ws[rg * 8 + 2 * p][d];
            const float p1 = ws[rg * 8 + 2 * p + 1][d];
            const uint32_t h2 = bf2(p0, p1);
            const float f0 = __uint_as_float(h2 << 16);
            const float f1 = __uint_as_float(h2 & 0xffff0000u);
            hi4[p] = h2;
            lo4[p] = bf2(p0 - f0, p1 - f1);
        }
        const size_t off = ((b * DD + d) * NN + j0l) * 2;
        *(uint4*)((char*)g_Bhi + off) = make_uint4(hi4[0], hi4[1], hi4[2], hi4[3]);
        *(uint4*)((char*)g_Blo + off) = make_uint4(lo4[0], lo4[1], lo4[2], lo4[3]);
    }
}

// ================= Kernel 2: masked-softmax x Wh, 16 warps, K-split x2 =================
// dyn smem: 4 ring buffers of 16 KB (hi @0, lo @8192 inside each) + align pad
#define BUFSZ 16384
#define DSM_BYTES (4 * BUFSZ + 1024)

__global__ void __launch_bounds__(512, 1) attn_kernel(const int* __restrict__ adj,
                                                      float* __restrict__ out) {
    extern __shared__ uint8_t dsm_raw[];
    uint32_t sb = smem_u32(dsm_raw);
    sb = (sb + 1023u) & ~1023u;

    const int tid = threadIdx.x, wid = tid >> 5, lid = tid & 31;
    const int wg = wid >> 3;        // 0: even tiles, 1: odd tiles
    const int wrow = wid & 7;       // row-block within CTA
    const int b = blockIdx.x >> 4;
    const int i0 = (blockIdx.x & 15) * 128;
    const int ibase = i0 + wrow * 16;
    const int r0 = lid >> 2, c0 = (lid & 3) * 2;

    const float s1_0 = g_s1[b * NN + ibase + r0];
    const float s1_1 = g_s1[b * NN + ibase + r0 + 8];
    float den0 = 0.f, den1 = 0.f;
    float4 acc[8];
#pragma unroll
    for (int nt = 0; nt < 8; nt++) acc[nt] = make_float4(0.f, 0.f, 0.f, 0.f);
    const float* s2base = g_s2 + b * NN;

    // ldmatrix addressing (B fragment layout identical to R3)
    uint32_t nrel[4], nxor[4], kh;
    {
        const int g = lid >> 3, rowin = lid & 7;
        kh = (uint32_t)((g & 1) * 16);
#pragma unroll
        for (int np = 0; np < 4; np++) {
            const int n = np * 16 + (g >> 1) * 8 + rowin;
            nrel[np] = (uint32_t)(n * 128);
            nxor[np] = (uint32_t)((n & 7) << 4);
        }
    }

    // staging addressing: 512 threads cover 64 d-rows x 8 chunks exactly
    const char* gbh = (const char*)g_Bhi + (size_t)b * DD * NN * 2;
    const char* gbl = (const char*)g_Blo + (size_t)b * DD * NN * 2;
    const int sd = tid >> 3, sch = tid & 7;
    const uint32_t ssw = sw128((uint32_t)(sd * 128 + sch * 16));
    const size_t sgo = (size_t)sd * NN * 2 + sch * 16;

    const int* arow0 = adj + (size_t)(b * NN + ibase + r0) * NN;
    const int* arow1 = arow0 + (size_t)8 * NN;

#define STAGE(t)                                                     \
    do {                                                             \
        const uint32_t dst = sb + (((t) & 3) * BUFSZ) + ssw;         \
        const size_t go = sgo + (size_t)(t) * (KTILE * 2);           \
        cpa16(dst, gbh + go);                                        \
        cpa16(dst + 8192, gbl + go);                                 \
    } while (0)

    STAGE(0);
    STAGE(1);
    cpa_commit();

    for (int i = 0; i < NKT / 2; i++) {
        cpa_wait0();
        __syncthreads();
        if (i < NKT / 2 - 1) {
            STAGE(2 * i + 2);
            STAGE(2 * i + 3);
            cpa_commit();
        }

        const int t = 2 * i + wg;
        const uint32_t bufb = sb + ((t & 3) * BUFSZ);
        const int jb0 = t * KTILE;

        int2 ajc0, ajc1, ajc2, ajc3;
        {
            const int jc = jb0 + c0;
            ajc0 = *(const int2*)(arow0 + jc);
            ajc1 = *(const int2*)(arow0 + jc + 8);
            ajc2 = *(const int2*)(arow1 + jc);
            ajc3 = *(const int2*)(arow1 + jc + 8);
        }

#pragma unroll
        for (int ks = 0; ks < 4; ks++) {
            int2 ajn0, ajn1, ajn2, ajn3;
            if (ks < 3) {
                const int jc = jb0 + (ks + 1) * 16 + c0;
                ajn0 = *(const int2*)(arow0 + jc);
                ajn1 = *(const int2*)(arow0 + jc + 8);
                ajn2 = *(const int2*)(arow1 + jc);
                ajn3 = *(const int2*)(arow1 + jc + 8);
            }

            const int jb = jb0 + ks * 16;
            const float2 s2a = *(const float2*)(s2base + jb + c0);
            const float2 s2b = *(const float2*)(s2base + jb + c0 + 8);

            const float p0 = pe(s1_0 + s2a.x, ajc0.x);
            const float p1 = pe(s1_0 + s2a.y, ajc0.y);
            const float p2 = pe(s1_0 + s2b.x, ajc1.x);
            const float p3 = pe(s1_0 + s2b.y, ajc1.y);
            const float p4 = pe(s1_1 + s2a.x, ajc2.x);
            const float p5 = pe(s1_1 + s2a.y, ajc2.y);
            const float p6 = pe(s1_1 + s2b.x, ajc3.x);
            const float p7 = pe(s1_1 + s2b.y, ajc3.y);
            den0 += (p0 + p1) + (p2 + p3);
            den1 += (p4 + p5) + (p6 + p7);

            uint32_t ah[4], al[4];
            {
                const uint32_t h0 = bf2(p0, p1), h1 = bf2(p4, p5);
                const uint32_t h2 = bf2(p2, p3), h3 = bf2(p6, p7);
                ah[0] = h0; ah[1] = h1; ah[2] = h2; ah[3] = h3;
                al[0] = bf2(p0 - __uint_as_float(h0 << 16),
                            p1 - __uint_as_float(h0 & 0xffff0000u));
                al[1] = bf2(p4 - __uint_as_float(h1 << 16),
                            p5 - __uint_as_float(h1 & 0xffff0000u));
                al[2] = bf2(p2 - __uint_as_float(h2 << 16),
                            p3 - __uint_as_float(h2 & 0xffff0000u));
                al[3] = bf2(p6 - __uint_as_float(h3 << 16),
                            p7 - __uint_as_float(h3 & 0xffff0000u));
            }

#pragma unroll
            for (int np = 0; np < 4; np++) {
                const uint32_t off = ((uint32_t)(ks * 32) + kh) ^ nxor[np];
                const uint32_t addr = bufb + nrel[np] + off;
                uint32_t h0, h1, h2, h3, l0, l1, l2, l3;
                ldmx4(h0, h1, h2, h3, addr);
                ldmx4(l0, l1, l2, l3, addr + 8192);
                float* d0 = (float*)&acc[2 * np];
                float* d1 = (float*)&acc[2 * np + 1];
                mma16816(d0, ah[0], ah[1], ah[2], ah[3], h0, h1);
                mma16816(d0, al[0], al[1], al[2], al[3], h0, h1);
                mma16816(d0, ah[0], ah[1], ah[2], ah[3], l0, l1);
                mma16816(d1, ah[0], ah[1], ah[2], ah[3], h2, h3);
                mma16816(d1, al[0], al[1], al[2], al[3], h2, h3);
                mma16816(d1, ah[0], ah[1], ah[2], ah[3], l2, l3);
            }
            if (ks < 3) {
                ajc0 = ajn0; ajc1 = ajn1; ajc2 = ajn2; ajc3 = ajn3;
            }
        }
    }

    // All compute (including ldmatrix reads of bufs 2/3) must finish before the
    // reduction region (which overlaps the ring buffers) is written.
    __syncthreads();

    // ---- cross-group reduction: wg1 dumps partials, wg0 combines + stores ----
    {
        float* redp = (float*)(dsm_raw + (sb - smem_u32(dsm_raw)));  // aligned base
        float* slot = redp + (size_t)(wrow * 32 + lid) * 36;
        if (wg == 1) {
#pragma unroll
            for (int nt = 0; nt < 8; nt++) *(float4*)(slot + nt * 4) = acc[nt];
            slot[32] = den0;
            slot[33] = den1;
        }
        __syncthreads();
        if (wg == 0) {
#pragma unroll
            for (int nt = 0; nt < 8; nt++) {
                const float4 v = *(const float4*)(slot + nt * 4);
                acc[nt].x += v.x; acc[nt].y += v.y;
                acc[nt].z += v.z; acc[nt].w += v.w;
            }
            den0 += slot[32];
            den1 += slot[33];

            den0 += __shfl_xor_sync(0xffffffffu, den0, 1);
            den0 += __shfl_xor_sync(0xffffffffu, den0, 2);
            den1 += __shfl_xor_sync(0xffffffffu, den1, 1);
            den1 += __shfl_xor_sync(0xffffffffu, den1, 2);
            const float inv0 = 1.0f / den0;
            const float inv1 = 1.0f / den1;

            float* o0 = out + (size_t)(b * NN + ibase + r0) * DD;
            float* o1 = o0 + (size_t)8 * DD;
#pragma unroll
            for (int nt = 0; nt < 8; nt++) {
                *(float2*)(o0 + nt * 8 + c0) =
                    make_float2(acc[nt].x * inv0, acc[nt].y * inv0);
                *(float2*)(o1 + nt * 8 + c0) =
                    make_float2(acc[nt].z * inv1, acc[nt].w * inv1);
            }
        }
    }
#undef STAGE
}

extern "C" void kernel_launch(void* const* d_in, const int* in_sizes, int n_in,
                              void* d_out, int out_size) {
    const float* h = nullptr;
    const int* adj = nullptr;
    const float* W = nullptr;
    const float* a = nullptr;
    for (int i = 0; i < n_in; i++) {
        const long long s = in_sizes[i];
        if (s == (long long)BB * NN * IND)      h   = (const float*)d_in[i];
        else if (s == (long long)BB * NN * NN)  adj = (const int*)d_in[i];
        else if (s == (long long)IND * DD)      W   = (const float*)d_in[i];
        else if (s == 2 * DD)                   a   = (const float*)d_in[i];
    }
    float* out = (float*)d_out;

    static bool attr_set = false;
    if (!attr_set) {
        cudaFuncSetAttribute(attn_kernel, cudaFuncAttributeMaxDynamicSharedMemorySize,
                             DSM_BYTES);
        attr_set = true;
    }

    wh_kernel<<<(BB * NN) / 32, 256>>>(h, W, a);
    attn_kernel<<<BB * (NN / 128), 512, DSM_BYTES>>>(adj, out);
}